// round 3
// baseline (speedup 1.0000x reference)
#include <cuda_runtime.h>
#include <cstdint>
#include <math.h>

// ======================= device scratch =======================
// Ypad: conv1x1 output in zero-padded 34-wide layout. [16][256][1408]
__device__ float g_Ypad[16 * 256 * 1408];
// Split conv3x3 weights (tf32 hi/lo): [tap(9)][co(512)][ci(256)]
__device__ float g_Wsp_hi[9 * 512 * 256];
__device__ float g_Wsp_lo[9 * 512 * 256];
// conv3x3 outputs (pre-BN, then normalized in place) [2][8][512][1024]
__device__ float g_F[2 * 8 * 512 * 1024];
// attention scores [8][512][512]
__device__ float g_S[8 * 512 * 512];
// BN partials: [t*512+co][144]  (b(8) x ntile(9) x ncol(2))
__device__ float g_psum[1024 * 144];
__device__ float g_psumq[1024 * 144];
__device__ float g_bn_a[1024];
__device__ float g_bn_c[1024];

#define LRELU 0.01f
#define BN_EPS 1e-5f
#define YSTRIDE 1408

__device__ __forceinline__ float tf32r(float x) {
    float r; asm("cvt.rna.tf32.f32 %0, %1;" : "=f"(r) : "f"(x)); return r;
}
__device__ __forceinline__ uint32_t fu(float x) { return __float_as_uint(x); }

#define MMA_TF32(d, a, b0v, b1v) \
    asm volatile("mma.sync.aligned.m16n8k8.row.col.f32.tf32.tf32.f32 " \
        "{%0,%1,%2,%3}, {%4,%5,%6,%7}, {%8,%9}, {%0,%1,%2,%3};" \
        : "+f"((d)[0]), "+f"((d)[1]), "+f"((d)[2]), "+f"((d)[3]) \
        : "r"((a)[0]), "r"((a)[1]), "r"((a)[2]), "r"((a)[3]), \
          "r"(b0v), "r"(b1v))

// ======================= setup kernels =======================
__global__ void zero_ypad_kernel() {
    int i = blockIdx.x * 256 + threadIdx.x;
    if (i < 16 * 256 * YSTRIDE) g_Ypad[i] = 0.f;
}

__global__ void wsplit_kernel(const float* __restrict__ w2) {
    int idx = blockIdx.x * 256 + threadIdx.x;  // co*2304 + ci*9 + tap
    if (idx >= 512 * 2304) return;
    int co = idx / 2304;
    int rem = idx - co * 2304;
    int ci = rem / 9;
    int tap = rem - ci * 9;
    float v = w2[idx];
    float hi = tf32r(v);
    g_Wsp_hi[((size_t)tap * 512 + co) * 256 + ci] = hi;
    g_Wsp_lo[((size_t)tap * 512 + co) * 256 + ci] = tf32r(v - hi);
}

// ======================= conv 1x1 (fp32 GEMM) -> Ypad ==========
__global__ __launch_bounds__(256) void conv1x1_kernel(
    const float* __restrict__ x1, const float* __restrict__ x2,
    const float* __restrict__ w1, const float* __restrict__ b1)
{
    int z = blockIdx.z;  // t*8 + b
    int t = z >> 3;
    const float* X = (t ? x2 : x1) + (size_t)(z & 7) * 512 * 1024;
    float* Yp = g_Ypad + (size_t)z * 256 * YSTRIDE;

    int m0 = blockIdx.y * 64, n0 = blockIdx.x * 64;
    __shared__ float sA[16][65];
    __shared__ __align__(16) float sB[16][64];

    int tid = threadIdx.x;
    int ty = tid >> 4, tx = tid & 15;
    float acc[4][4] = {};

    for (int k0 = 0; k0 < 512; k0 += 16) {
        #pragma unroll
        for (int i = 0; i < 4; i++) {
            int idx = tid + i * 256;
            int m = idx >> 4, k = idx & 15;
            sA[k][m] = w1[(size_t)(m0 + m) * 512 + k0 + k];
        }
        #pragma unroll
        for (int i = 0; i < 4; i++) {
            int idx = tid + i * 256;
            int k = idx >> 6, n = idx & 63;
            sB[k][n] = X[(size_t)(k0 + k) * 1024 + n0 + n];
        }
        __syncthreads();
        #pragma unroll
        for (int k = 0; k < 16; k++) {
            float a0 = sA[k][ty * 4 + 0];
            float a1 = sA[k][ty * 4 + 1];
            float a2 = sA[k][ty * 4 + 2];
            float a3 = sA[k][ty * 4 + 3];
            float4 bb = *(const float4*)&sB[k][tx * 4];
            acc[0][0] += a0 * bb.x; acc[0][1] += a0 * bb.y; acc[0][2] += a0 * bb.z; acc[0][3] += a0 * bb.w;
            acc[1][0] += a1 * bb.x; acc[1][1] += a1 * bb.y; acc[1][2] += a1 * bb.z; acc[1][3] += a1 * bb.w;
            acc[2][0] += a2 * bb.x; acc[2][1] += a2 * bb.y; acc[2][2] += a2 * bb.z; acc[2][3] += a2 * bb.w;
            acc[3][0] += a3 * bb.x; acc[3][1] += a3 * bb.y; acc[3][2] += a3 * bb.z; acc[3][3] += a3 * bb.w;
        }
        __syncthreads();
    }
    #pragma unroll
    for (int i = 0; i < 4; i++) {
        int m = m0 + ty * 4 + i;
        float bias = b1[m];
        #pragma unroll
        for (int j = 0; j < 4; j++) {
            int p = n0 + tx * 4 + j;
            int h = p >> 5, w = p & 31;
            Yp[(size_t)m * YSTRIDE + 99 + h * 34 + w] = acc[i][j] + bias;
        }
    }
}

// ======================= conv 3x3 via mma.sync tf32 3x-split ==========
// CTA: D[128 co][128 n'] per image z. 72 chunks = 9 taps x 8 ci-chunks(32).
// Warp grid 4(m) x 2(n): warp tile 32m x 64n. mma m16n8k8.
// Shared (64KB): sAhi[4096] sAlo[4096] sBhi[4096] sBlo[4096] floats
//  A frag idx: ((mblk*4+s)*32 + lane)*4 + reg
//  B frag idx: ((nblk*2+s2)*32 + lane)*4 + sp*2 + reg
#define SMEM_CONV (4 * 4096 * 4)

__global__ __launch_bounds__(256, 2) void conv3x3_mma_kernel(const float* __restrict__ b2)
{
    extern __shared__ __align__(16) float smem[];
    float* sAhi = smem;
    float* sAlo = smem + 4096;
    float* sBhi = smem + 8192;
    float* sBlo = smem + 12288;

    int tid = threadIdx.x;
    int wid = tid >> 5, lane = tid & 31;
    int ntile = blockIdx.x;
    int m0 = blockIdx.y * 128;
    int z = blockIdx.z;
    int nbase = ntile * 128;
    const float* Yz = g_Ypad + (size_t)z * 256 * YSTRIDE;

    int wm = (wid & 3) * 32;        // warp m offset in CTA tile
    int wn = (wid >> 2) * 64;       // warp n offset
    int g = lane >> 2, tq = lane & 3;

    float acc[2][8][4];
    #pragma unroll
    for (int i = 0; i < 2; i++)
        #pragma unroll
        for (int j = 0; j < 8; j++)
            #pragma unroll
            for (int r = 0; r < 4; r++) acc[i][j][r] = 0.f;

    for (int tap = 0; tap < 9; tap++) {
        int dh = tap / 3, dw = tap - dh * 3;
        const float* Bsrc = Yz + 29 + nbase + dh * 34 + dw;
        for (int ci0 = 0; ci0 < 256; ci0 += 32) {
            // ---- stage A (weights hi/lo, already tf32) ----
            #pragma unroll
            for (int it = 0; it < 4; it++) {
                int task = tid + it * 256;
                int m = task >> 3;
                int k0 = (task & 7) * 4;
                size_t goff = ((size_t)tap * 512 + m0 + m) * 256 + ci0 + k0;
                float4 vh = *(const float4*)(g_Wsp_hi + goff);
                float4 vl = *(const float4*)(g_Wsp_lo + goff);
                int mblk = m >> 4, mm = m & 15;
                int lb = (mm & 7) << 2;
                const float* ph = (const float*)&vh;
                const float* pl = (const float*)&vl;
                #pragma unroll
                for (int c = 0; c < 4; c++) {
                    int k = k0 + c;
                    int s = k >> 3;
                    int idx = ((mblk * 4 + s) * 32 + (lb | (k & 3))) * 4
                              + ((mm >> 3) | (((k >> 2) & 1) << 1));
                    sAhi[idx] = ph[c];
                    sAlo[idx] = pl[c];
                }
            }
            // ---- stage B (activations, split on the fly) ----
            #pragma unroll
            for (int p = 0; p < 4; p++) {
                int k = (tid >> 5) + p * 8;
                int n0 = lane * 4;
                const float* src = Bsrc + (size_t)(ci0 + k) * YSTRIDE + n0;
                int s2 = k >> 4, sp = (k >> 3) & 1, reg = (k >> 2) & 1;
                #pragma unroll
                for (int c = 0; c < 4; c++) {
                    float v = src[c];
                    float h = tf32r(v);
                    float l = tf32r(v - h);
                    int n = n0 + c;
                    int idx = (((n >> 3) * 2 + s2) * 32 + (((n & 7) << 2) | (k & 3))) * 4
                              + sp * 2 + reg;
                    sBhi[idx] = h;
                    sBlo[idx] = l;
                }
            }
            __syncthreads();

            // ---- mma ----
            #pragma unroll
            for (int s2 = 0; s2 < 2; s2++) {
                uint32_t ah[2][2][4], al[2][2][4];
                #pragma unroll
                for (int i = 0; i < 2; i++) {
                    int mblk = (wm >> 4) + i;
                    #pragma unroll
                    for (int sp = 0; sp < 2; sp++) {
                        int s = s2 * 2 + sp;
                        float4 vh = *(const float4*)&sAhi[((mblk * 4 + s) * 32 + lane) * 4];
                        float4 vl = *(const float4*)&sAlo[((mblk * 4 + s) * 32 + lane) * 4];
                        ah[i][sp][0] = fu(vh.x); ah[i][sp][1] = fu(vh.y);
                        ah[i][sp][2] = fu(vh.z); ah[i][sp][3] = fu(vh.w);
                        al[i][sp][0] = fu(vl.x); al[i][sp][1] = fu(vl.y);
                        al[i][sp][2] = fu(vl.z); al[i][sp][3] = fu(vl.w);
                    }
                }
                #pragma unroll
                for (int j = 0; j < 8; j++) {
                    int nblk = (wn >> 3) + j;
                    float4 bh = *(const float4*)&sBhi[((nblk * 2 + s2) * 32 + lane) * 4];
                    float4 bl = *(const float4*)&sBlo[((nblk * 2 + s2) * 32 + lane) * 4];
                    #pragma unroll
                    for (int i = 0; i < 2; i++) {
                        MMA_TF32(acc[i][j], ah[i][0], fu(bh.x), fu(bh.y));
                        MMA_TF32(acc[i][j], al[i][0], fu(bh.x), fu(bh.y));
                        MMA_TF32(acc[i][j], ah[i][0], fu(bl.x), fu(bl.y));
                        MMA_TF32(acc[i][j], ah[i][1], fu(bh.z), fu(bh.w));
                        MMA_TF32(acc[i][j], al[i][1], fu(bh.z), fu(bh.w));
                        MMA_TF32(acc[i][j], ah[i][1], fu(bl.z), fu(bl.w));
                    }
                }
            }
            __syncthreads();
        }
    }

    // ---- epilogue: bias + LeakyReLU + store F + BN partials ----
    int timg = z >> 3, b = z & 7;
    int ncol = wid >> 2;
    float bias[2][2], psv[2][2] = {}, pqv[2][2] = {};
    #pragma unroll
    for (int i = 0; i < 2; i++)
        #pragma unroll
        for (int rh = 0; rh < 2; rh++)
            bias[i][rh] = b2[m0 + wm + i * 16 + g + rh * 8];

    #pragma unroll
    for (int i = 0; i < 2; i++) {
        #pragma unroll
        for (int j = 0; j < 8; j++) {
            #pragma unroll
            for (int r = 0; r < 4; r++) {
                int rh = r >> 1, c = r & 1;
                int m = wm + i * 16 + g + rh * 8;
                int np = nbase + wn + j * 8 + 2 * tq + c;
                int row = np / 34;
                int col = np - row * 34;
                if (row >= 1 && row <= 32 && col >= 1 && col <= 32) {
                    float v = acc[i][j][r] + bias[i][rh];
                    v = v > 0.f ? v : LRELU * v;
                    g_F[((size_t)z * 512 + m0 + m) * 1024 + (row - 1) * 32 + (col - 1)] = v;
                    psv[i][rh] += v;
                    pqv[i][rh] += v * v;
                }
            }
        }
    }
    // quad reduce (over tq) and write partials
    #pragma unroll
    for (int i = 0; i < 2; i++) {
        #pragma unroll
        for (int rh = 0; rh < 2; rh++) {
            float s = psv[i][rh], q = pqv[i][rh];
            s += __shfl_xor_sync(0xffffffffu, s, 1);
            s += __shfl_xor_sync(0xffffffffu, s, 2);
            q += __shfl_xor_sync(0xffffffffu, q, 1);
            q += __shfl_xor_sync(0xffffffffu, q, 2);
            if (tq == 0) {
                int ch = timg * 512 + m0 + wm + i * 16 + g + rh * 8;
                int slot = (b * 9 + ntile) * 2 + ncol;
                g_psum [(size_t)ch * 144 + slot] = s;
                g_psumq[(size_t)ch * 144 + slot] = q;
            }
        }
    }
}

// ======================= BN stats / apply =======================
__global__ void bn_stats_kernel(const float* __restrict__ gamma,
                                const float* __restrict__ bn_bias)
{
    int i = blockIdx.x * blockDim.x + threadIdx.x;
    if (i >= 1024) return;
    float s = 0.f, q = 0.f;
    #pragma unroll 8
    for (int p = 0; p < 144; p++) {
        s += g_psum [(size_t)i * 144 + p];
        q += g_psumq[(size_t)i * 144 + p];
    }
    const float inv_n = 1.0f / 8192.0f;
    float mean = s * inv_n;
    float var = q * inv_n - mean * mean;
    float a = gamma[i & 511] * rsqrtf(var + BN_EPS);
    g_bn_a[i] = a;
    g_bn_c[i] = bn_bias[i & 511] - mean * a;
}

__global__ void bn_apply_kernel()
{
    int idx = blockIdx.x * 256 + threadIdx.x;
    int ch = (idx >> 10) & 511;
    int t = idx >> 22;
    float v = g_F[idx];
    g_F[idx] = v * g_bn_a[t * 512 + ch] + g_bn_c[t * 512 + ch];
}

// ======================= scores GEMM (fp32) =======================
__global__ __launch_bounds__(256) void scores_kernel()
{
    int b = blockIdx.z;
    const float* A = g_F + (size_t)b * 512 * 1024;
    const float* B = g_F + (size_t)(8 + b) * 512 * 1024;
    float* S = g_S + (size_t)b * 512 * 512;

    int m0 = blockIdx.y * 64, n0 = blockIdx.x * 64;
    __shared__ float sA[16][65];
    __shared__ float sB[16][65];

    int tid = threadIdx.x;
    int ty = tid >> 4, tx = tid & 15;
    float acc[4][4] = {};

    for (int k0 = 0; k0 < 1024; k0 += 16) {
        #pragma unroll
        for (int i = 0; i < 4; i++) {
            int idx = tid + i * 256;
            int m = idx >> 4, k = idx & 15;
            sA[k][m] = A[(size_t)(m0 + m) * 1024 + k0 + k];
            sB[k][m] = B[(size_t)(n0 + m) * 1024 + k0 + k];
        }
        __syncthreads();
        #pragma unroll
        for (int k = 0; k < 16; k++) {
            float a0 = sA[k][ty * 4 + 0], a1 = sA[k][ty * 4 + 1];
            float a2 = sA[k][ty * 4 + 2], a3 = sA[k][ty * 4 + 3];
            float b0 = sB[k][tx * 4 + 0], b1 = sB[k][tx * 4 + 1];
            float b2 = sB[k][tx * 4 + 2], b3 = sB[k][tx * 4 + 3];
            acc[0][0] += a0 * b0; acc[0][1] += a0 * b1; acc[0][2] += a0 * b2; acc[0][3] += a0 * b3;
            acc[1][0] += a1 * b0; acc[1][1] += a1 * b1; acc[1][2] += a1 * b2; acc[1][3] += a1 * b3;
            acc[2][0] += a2 * b0; acc[2][1] += a2 * b1; acc[2][2] += a2 * b2; acc[2][3] += a2 * b3;
            acc[3][0] += a3 * b0; acc[3][1] += a3 * b1; acc[3][2] += a3 * b2; acc[3][3] += a3 * b3;
        }
        __syncthreads();
    }
    #pragma unroll
    for (int i = 0; i < 4; i++)
        #pragma unroll
        for (int j = 0; j < 4; j++)
            S[(size_t)(m0 + ty * 4 + i) * 512 + n0 + tx * 4 + j] = acc[i][j];
}

// ======================= softmax =======================
__global__ void softmax_kernel()
{
    int row = blockIdx.x;
    float* s = g_S + (size_t)row * 512;
    int tid = threadIdx.x;

    float v0 = s[tid], v1 = s[tid + 256];
    float m = fmaxf(v0, v1);
    __shared__ float red[8];
    #pragma unroll
    for (int o = 16; o > 0; o >>= 1)
        m = fmaxf(m, __shfl_xor_sync(0xffffffffu, m, o));
    if ((tid & 31) == 0) red[tid >> 5] = m;
    __syncthreads();
    float M = fmaxf(fmaxf(fmaxf(red[0], red[1]), fmaxf(red[2], red[3])),
                    fmaxf(fmaxf(red[4], red[5]), fmaxf(red[6], red[7])));
    __syncthreads();

    float e0 = expf(v0 - M), e1 = expf(v1 - M);
    float sum = e0 + e1;
    #pragma unroll
    for (int o = 16; o > 0; o >>= 1)
        sum += __shfl_xor_sync(0xffffffffu, sum, o);
    if ((tid & 31) == 0) red[tid >> 5] = sum;
    __syncthreads();
    float T = red[0] + red[1] + red[2] + red[3] + red[4] + red[5] + red[6] + red[7];
    float inv = 1.0f / T;
    s[tid] = e0 * inv;
    s[tid + 256] = e1 * inv;
}

// ======================= out GEMM (fp32) =======================
__global__ __launch_bounds__(256) void out_kernel(
    const float* __restrict__ x, const float* __restrict__ beta,
    float* __restrict__ out)
{
    int b = blockIdx.z;
    const float* A = g_S + (size_t)b * 512 * 512;
    const float* X = x + (size_t)b * 512 * 1024;
    float* O = out + (size_t)b * 512 * 1024;

    int m0 = blockIdx.y * 64, n0 = blockIdx.x * 64;
    __shared__ float sA[16][65];
    __shared__ __align__(16) float sB[16][64];

    int tid = threadIdx.x;
    int ty = tid >> 4, tx = tid & 15;
    float acc[4][4] = {};

    for (int k0 = 0; k0 < 512; k0 += 16) {
        #pragma unroll
        for (int i = 0; i < 4; i++) {
            int idx = tid + i * 256;
            int m = idx >> 4, k = idx & 15;
            sA[k][m] = A[(size_t)(m0 + m) * 512 + k0 + k];
        }
        #pragma unroll
        for (int i = 0; i < 4; i++) {
            int idx = tid + i * 256;
            int k = idx >> 6, n = idx & 63;
            sB[k][n] = X[(size_t)(k0 + k) * 1024 + n0 + n];
        }
        __syncthreads();
        #pragma unroll
        for (int k = 0; k < 16; k++) {
            float a0 = sA[k][ty * 4 + 0];
            float a1 = sA[k][ty * 4 + 1];
            float a2 = sA[k][ty * 4 + 2];
            float a3 = sA[k][ty * 4 + 3];
            float4 bb = *(const float4*)&sB[k][tx * 4];
            acc[0][0] += a0 * bb.x; acc[0][1] += a0 * bb.y; acc[0][2] += a0 * bb.z; acc[0][3] += a0 * bb.w;
            acc[1][0] += a1 * bb.x; acc[1][1] += a1 * bb.y; acc[1][2] += a1 * bb.z; acc[1][3] += a1 * bb.w;
            acc[2][0] += a2 * bb.x; acc[2][1] += a2 * bb.y; acc[2][2] += a2 * bb.z; acc[2][3] += a2 * bb.w;
            acc[3][0] += a3 * bb.x; acc[3][1] += a3 * bb.y; acc[3][2] += a3 * bb.z; acc[3][3] += a3 * bb.w;
        }
        __syncthreads();
    }
    float bt = beta[0];
    #pragma unroll
    for (int i = 0; i < 4; i++)
        #pragma unroll
        for (int j = 0; j < 4; j++)
            O[(size_t)(m0 + ty * 4 + i) * 1024 + n0 + tx * 4 + j] = bt * acc[i][j];
}

// ======================= launch =======================
extern "C" void kernel_launch(void* const* d_in, const int* in_sizes, int n_in,
                              void* d_out, int out_size)
{
    const float* x     = (const float*)d_in[0];
    const float* x1    = (const float*)d_in[1];
    const float* x2    = (const float*)d_in[2];
    const float* w1    = (const float*)d_in[3];
    const float* b1    = (const float*)d_in[4];
    const float* w2    = (const float*)d_in[5];
    const float* b2    = (const float*)d_in[6];
    const float* gamma = (const float*)d_in[7];
    const float* bnb   = (const float*)d_in[8];
    const float* beta  = (const float*)d_in[9];
    float* out = (float*)d_out;

    static int smem_set = 0;
    if (!smem_set) {
        cudaFuncSetAttribute(conv3x3_mma_kernel,
                             cudaFuncAttributeMaxDynamicSharedMemorySize, SMEM_CONV);
        smem_set = 1;
    }

    zero_ypad_kernel<<<(16 * 256 * YSTRIDE + 255) / 256, 256>>>();
    wsplit_kernel<<<(512 * 2304 + 255) / 256, 256>>>(w2);

    conv1x1_kernel<<<dim3(16, 4, 16), 256>>>(x1, x2, w1, b1);

    // ntile(9) x co_tile(4) x image(16)
    conv3x3_mma_kernel<<<dim3(9, 4, 16), 256, SMEM_CONV>>>(b2);

    bn_stats_kernel<<<4, 256>>>(gamma, bnb);
    bn_apply_kernel<<<(2 * 8 * 512 * 1024) / 256, 256>>>();

    scores_kernel<<<dim3(8, 8, 8), 256>>>();
    softmax_kernel<<<4096, 256>>>();

    out_kernel<<<dim3(16, 8, 8), 256>>>(x, beta, out);
}

// round 4
// speedup vs baseline: 2.2642x; 2.2642x over previous
#include <cuda_runtime.h>
#include <cstdint>
#include <math.h>

// ======================= device scratch =======================
// Ypad: conv1x1 output in zero-padded 34-wide layout. [16][256][1408]
__device__ __align__(16) float g_Ypad[16 * 256 * 1408];
// conv3x3 weights reordered fragment-major: [tap9][cc8][m0t4][4096]
__device__ __align__(16) float g_Aord[9 * 8 * 4 * 4096];
// conv3x3 outputs (pre-BN, then normalized in place) [2][8][512][1024]
__device__ float g_F[2 * 8 * 512 * 1024];
// attention scores [8][512][512]
__device__ float g_S[8 * 512 * 512];
// BN partials: [t*512+co][144]  (b(8) x ntile(9) x ncol(2))
__device__ float g_psum[1024 * 144];
__device__ float g_psumq[1024 * 144];
__device__ float g_bn_a[1024];
__device__ float g_bn_c[1024];

#define LRELU 0.01f
#define BN_EPS 1e-5f
#define YSTRIDE 1408
#define BSTRIDE 204

__device__ __forceinline__ float tf32r(float x) {
    float r; asm("cvt.rna.tf32.f32 %0, %1;" : "=f"(r) : "f"(x)); return r;
}
__device__ __forceinline__ uint32_t fu(float x) { return __float_as_uint(x); }
__device__ __forceinline__ uint32_t smem_u32(const void* p) {
    uint32_t a;
    asm("{ .reg .u64 t; cvta.to.shared.u64 t, %1; cvt.u32.u64 %0, t; }" : "=r"(a) : "l"(p));
    return a;
}

#define MMA_TF32(d, a0, a1, a2, a3, b0v, b1v) \
    asm volatile("mma.sync.aligned.m16n8k8.row.col.f32.tf32.tf32.f32 " \
        "{%0,%1,%2,%3}, {%4,%5,%6,%7}, {%8,%9}, {%0,%1,%2,%3};" \
        : "+f"((d)[0]), "+f"((d)[1]), "+f"((d)[2]), "+f"((d)[3]) \
        : "r"(a0), "r"(a1), "r"(a2), "r"(a3), "r"(b0v), "r"(b1v))

#define CP16(saddr, gptr) \
    asm volatile("cp.async.ca.shared.global [%0], [%1], 16;" \
                 :: "r"((uint32_t)(saddr)), "l"(gptr) : "memory")
#define CP_COMMIT() asm volatile("cp.async.commit_group;" ::: "memory")
#define CP_WAIT_ALL() asm volatile("cp.async.wait_group 0;" ::: "memory")

// ======================= setup kernels =======================
__global__ void zero_ypad_kernel() {
    int i = blockIdx.x * 256 + threadIdx.x;
    if (i < 16 * 256 * YSTRIDE) g_Ypad[i] = 0.f;
}

// Reorder w2 into fragment-major: [tap][cc][m0t][mblk8][s4][lane32][c4]
__global__ void areorder_kernel(const float* __restrict__ w2) {
    int idx = blockIdx.x * 256 + threadIdx.x;
    if (idx >= 9 * 8 * 4 * 4096) return;
    int c    = idx & 3;
    int lane = (idx >> 2) & 31;
    int s    = (idx >> 7) & 3;
    int mblk = (idx >> 9) & 7;
    int m0t  = (idx >> 12) & 3;
    int cc   = (idx >> 14) & 7;
    int tap  = idx >> 17;
    int m = mblk * 16 + (lane >> 2) + (c & 1) * 8;
    int k = (lane & 3) + (c >> 1) * 4;
    int co = m0t * 128 + m;
    int ci = cc * 32 + s * 8 + k;
    g_Aord[idx] = w2[(size_t)co * 2304 + ci * 9 + tap];
}

// ======================= conv 1x1 (fp32 GEMM) -> Ypad ==========
__global__ __launch_bounds__(256) void conv1x1_kernel(
    const float* __restrict__ x1, const float* __restrict__ x2,
    const float* __restrict__ w1, const float* __restrict__ b1)
{
    int z = blockIdx.z;  // t*8 + b
    int t = z >> 3;
    const float* X = (t ? x2 : x1) + (size_t)(z & 7) * 512 * 1024;
    float* Yp = g_Ypad + (size_t)z * 256 * YSTRIDE;

    int m0 = blockIdx.y * 64, n0 = blockIdx.x * 64;
    __shared__ float sA[16][65];
    __shared__ __align__(16) float sB[16][64];

    int tid = threadIdx.x;
    int ty = tid >> 4, tx = tid & 15;
    float acc[4][4] = {};

    for (int k0 = 0; k0 < 512; k0 += 16) {
        #pragma unroll
        for (int i = 0; i < 4; i++) {
            int idx = tid + i * 256;
            int m = idx >> 4, k = idx & 15;
            sA[k][m] = w1[(size_t)(m0 + m) * 512 + k0 + k];
        }
        #pragma unroll
        for (int i = 0; i < 4; i++) {
            int idx = tid + i * 256;
            int k = idx >> 6, n = idx & 63;
            sB[k][n] = X[(size_t)(k0 + k) * 1024 + n0 + n];
        }
        __syncthreads();
        #pragma unroll
        for (int k = 0; k < 16; k++) {
            float a0 = sA[k][ty * 4 + 0];
            float a1 = sA[k][ty * 4 + 1];
            float a2 = sA[k][ty * 4 + 2];
            float a3 = sA[k][ty * 4 + 3];
            float4 bb = *(const float4*)&sB[k][tx * 4];
            acc[0][0] += a0 * bb.x; acc[0][1] += a0 * bb.y; acc[0][2] += a0 * bb.z; acc[0][3] += a0 * bb.w;
            acc[1][0] += a1 * bb.x; acc[1][1] += a1 * bb.y; acc[1][2] += a1 * bb.z; acc[1][3] += a1 * bb.w;
            acc[2][0] += a2 * bb.x; acc[2][1] += a2 * bb.y; acc[2][2] += a2 * bb.z; acc[2][3] += a2 * bb.w;
            acc[3][0] += a3 * bb.x; acc[3][1] += a3 * bb.y; acc[3][2] += a3 * bb.z; acc[3][3] += a3 * bb.w;
        }
        __syncthreads();
    }
    #pragma unroll
    for (int i = 0; i < 4; i++) {
        int m = m0 + ty * 4 + i;
        float bias = b1[m];
        #pragma unroll
        for (int j = 0; j < 4; j++) {
            int p = n0 + tx * 4 + j;
            int h = p >> 5, w = p & 31;
            Yp[(size_t)m * YSTRIDE + 99 + h * 34 + w] = acc[i][j] + bias;
        }
    }
}

// ======================= conv 3x3 via mma.sync tf32 (v2) ==========
// CTA: D[128 co][128 n']. Chunks: cc(8) outer x tap(9) inner.
// A: fragment-major, double-buffered via cp.async (2 x 16KB).
// B: plain fp32 rows [32k][204], halo 70, staged once per cc, double-buffered (2 x 25.5KB).
// hi/lo tf32 split computed in registers at use.
#define SMEM_CONV ((2 * 4096 + 2 * 32 * BSTRIDE) * 4)

__global__ __launch_bounds__(256, 2) void conv3x3_mma_kernel(const float* __restrict__ b2)
{
    extern __shared__ __align__(16) float smem[];
    float* sA = smem;                      // 2 x 4096
    float* sB = smem + 2 * 4096;           // 2 x 6528
    uint32_t sA32 = smem_u32(sA);
    uint32_t sB32 = smem_u32(sB);

    int tid = threadIdx.x;
    int wid = tid >> 5, lane = tid & 31;
    int g = lane >> 2, tq = lane & 3;
    int ntile = blockIdx.x;              // 0..8
    int m0y = blockIdx.y;                // 0..3
    int m0 = m0y * 128;
    int z = blockIdx.z;
    int nbase = ntile * 128;
    const float* Yz = g_Ypad + (size_t)z * 256 * YSTRIDE;

    int aoff = (29 + nbase) & 3;
    int colbase = (29 + nbase) - aoff;

    int wm = (wid & 3) * 32;
    int wn = (wid >> 2) * 64;

    float acc[2][8][4];
    #pragma unroll
    for (int i = 0; i < 2; i++)
        #pragma unroll
        for (int j = 0; j < 8; j++)
            #pragma unroll
            for (int r = 0; r < 4; r++) acc[i][j][r] = 0.f;

    // ---- staging helpers ----
    // chunk ids: it = cc*9 + tap
    auto stageA = [&](int it) {
        int tap = it % 9, cc = it / 9;
        const float4* gA = (const float4*)(g_Aord + (((size_t)tap * 8 + cc) * 4 + m0y) * 4096);
        uint32_t base = sA32 + (uint32_t)((it & 1) * 4096) * 4;
        #pragma unroll
        for (int v = 0; v < 4; v++) {
            int e = tid + v * 256;
            CP16(base + e * 16, gA + e);
        }
    };
    auto stageB = [&](int cc) {
        uint32_t base = sB32 + (uint32_t)((cc & 1) * 32 * BSTRIDE) * 4;
        #pragma unroll
        for (int v = 0; v < 7; v++) {
            int i = tid + v * 256;
            if (i < 32 * 51) {
                int row = i / 51;
                int c4 = i - row * 51;
                const float* gp = Yz + (size_t)(cc * 32 + row) * YSTRIDE + colbase + c4 * 4;
                CP16(base + (row * BSTRIDE + c4 * 4) * 4, gp);
            }
        }
    };

    // prologue: chunk 0 (A) + cc 0 (B)
    stageA(0);
    stageB(0);
    CP_COMMIT();

    for (int it = 0; it < 72; ++it) {
        int tap = it % 9, cc = it / 9;
        int dh = tap / 3, dw = tap - dh * 3;

        CP_WAIT_ALL();
        __syncthreads();

        // prefetch next chunk
        if (it < 71) {
            stageA(it + 1);
            if (tap == 8) stageB(cc + 1);
        }
        CP_COMMIT();

        const float* sAp = sA + (it & 1) * 4096;
        const float* sBp = sB + (cc & 1) * 32 * BSTRIDE + aoff + dh * 34 + dw;

        #pragma unroll
        for (int s = 0; s < 4; s++) {
            // A fragments (plain fp32 -> split in regs)
            uint32_t ah[2][4], al[2][4];
            #pragma unroll
            for (int i = 0; i < 2; i++) {
                int mblk = (wm >> 4) + i;
                float4 av = *(const float4*)&sAp[((mblk * 4 + s) * 32 + lane) * 4];
                float h0 = tf32r(av.x), h1 = tf32r(av.y), h2 = tf32r(av.z), h3 = tf32r(av.w);
                ah[i][0] = fu(h0); ah[i][1] = fu(h1); ah[i][2] = fu(h2); ah[i][3] = fu(h3);
                al[i][0] = fu(av.x - h0); al[i][1] = fu(av.y - h1);
                al[i][2] = fu(av.z - h2); al[i][3] = fu(av.w - h3);
            }
            const float* brow = sBp + (s * 8 + tq) * BSTRIDE + wn + g;
            #pragma unroll
            for (int j = 0; j < 8; j++) {
                float b0 = brow[j * 8];
                float b1 = brow[j * 8 + 4 * BSTRIDE];
                float bh0 = tf32r(b0), bh1 = tf32r(b1);
                uint32_t ubh0 = fu(bh0), ubh1 = fu(bh1);
                uint32_t ubl0 = fu(b0 - bh0), ubl1 = fu(b1 - bh1);
                #pragma unroll
                for (int i = 0; i < 2; i++) {
                    MMA_TF32(acc[i][j], ah[i][0], ah[i][1], ah[i][2], ah[i][3], ubh0, ubh1);
                    MMA_TF32(acc[i][j], al[i][0], al[i][1], al[i][2], al[i][3], ubh0, ubh1);
                    MMA_TF32(acc[i][j], ah[i][0], ah[i][1], ah[i][2], ah[i][3], ubl0, ubl1);
                }
            }
        }
    }

    // ---- epilogue: bias + LeakyReLU + store F + BN partials ----
    int timg = z >> 3, b = z & 7;
    int ncol = wid >> 2;
    float bias[2][2], psv[2][2] = {}, pqv[2][2] = {};
    #pragma unroll
    for (int i = 0; i < 2; i++)
        #pragma unroll
        for (int rh = 0; rh < 2; rh++)
            bias[i][rh] = b2[m0 + wm + i * 16 + g + rh * 8];

    #pragma unroll
    for (int i = 0; i < 2; i++) {
        #pragma unroll
        for (int j = 0; j < 8; j++) {
            #pragma unroll
            for (int r = 0; r < 4; r++) {
                int rh = r >> 1, c = r & 1;
                int m = wm + i * 16 + g + rh * 8;
                int np = nbase + wn + j * 8 + 2 * tq + c;
                int row = np / 34;
                int col = np - row * 34;
                if (row >= 1 && row <= 32 && col >= 1 && col <= 32) {
                    float v = acc[i][j][r] + bias[i][rh];
                    v = v > 0.f ? v : LRELU * v;
                    g_F[((size_t)z * 512 + m0 + m) * 1024 + (row - 1) * 32 + (col - 1)] = v;
                    psv[i][rh] += v;
                    pqv[i][rh] += v * v;
                }
            }
        }
    }
    #pragma unroll
    for (int i = 0; i < 2; i++) {
        #pragma unroll
        for (int rh = 0; rh < 2; rh++) {
            float s = psv[i][rh], q = pqv[i][rh];
            s += __shfl_xor_sync(0xffffffffu, s, 1);
            s += __shfl_xor_sync(0xffffffffu, s, 2);
            q += __shfl_xor_sync(0xffffffffu, q, 1);
            q += __shfl_xor_sync(0xffffffffu, q, 2);
            if (tq == 0) {
                int ch = timg * 512 + m0 + wm + i * 16 + g + rh * 8;
                int slot = (b * 9 + ntile) * 2 + ncol;
                g_psum [(size_t)ch * 144 + slot] = s;
                g_psumq[(size_t)ch * 144 + slot] = q;
            }
        }
    }
}

// ======================= BN stats / apply =======================
__global__ void bn_stats_kernel(const float* __restrict__ gamma,
                                const float* __restrict__ bn_bias)
{
    int i = blockIdx.x * blockDim.x + threadIdx.x;
    if (i >= 1024) return;
    float s = 0.f, q = 0.f;
    #pragma unroll 8
    for (int p = 0; p < 144; p++) {
        s += g_psum [(size_t)i * 144 + p];
        q += g_psumq[(size_t)i * 144 + p];
    }
    const float inv_n = 1.0f / 8192.0f;
    float mean = s * inv_n;
    float var = q * inv_n - mean * mean;
    float a = gamma[i & 511] * rsqrtf(var + BN_EPS);
    g_bn_a[i] = a;
    g_bn_c[i] = bn_bias[i & 511] - mean * a;
}

__global__ void bn_apply_kernel()
{
    int idx = blockIdx.x * 256 + threadIdx.x;
    int ch = (idx >> 10) & 511;
    int t = idx >> 22;
    float v = g_F[idx];
    g_F[idx] = v * g_bn_a[t * 512 + ch] + g_bn_c[t * 512 + ch];
}

// ======================= scores GEMM (fp32) =======================
__global__ __launch_bounds__(256) void scores_kernel()
{
    int b = blockIdx.z;
    const float* A = g_F + (size_t)b * 512 * 1024;
    const float* B = g_F + (size_t)(8 + b) * 512 * 1024;
    float* S = g_S + (size_t)b * 512 * 512;

    int m0 = blockIdx.y * 64, n0 = blockIdx.x * 64;
    __shared__ float sA[16][65];
    __shared__ float sB[16][65];

    int tid = threadIdx.x;
    int ty = tid >> 4, tx = tid & 15;
    float acc[4][4] = {};

    for (int k0 = 0; k0 < 1024; k0 += 16) {
        #pragma unroll
        for (int i = 0; i < 4; i++) {
            int idx = tid + i * 256;
            int m = idx >> 4, k = idx & 15;
            sA[k][m] = A[(size_t)(m0 + m) * 1024 + k0 + k];
            sB[k][m] = B[(size_t)(n0 + m) * 1024 + k0 + k];
        }
        __syncthreads();
        #pragma unroll
        for (int k = 0; k < 16; k++) {
            float a0 = sA[k][ty * 4 + 0], a1 = sA[k][ty * 4 + 1];
            float a2 = sA[k][ty * 4 + 2], a3 = sA[k][ty * 4 + 3];
            float b0 = sB[k][tx * 4 + 0], b1 = sB[k][tx * 4 + 1];
            float b2 = sB[k][tx * 4 + 2], b3 = sB[k][tx * 4 + 3];
            acc[0][0] += a0 * b0; acc[0][1] += a0 * b1; acc[0][2] += a0 * b2; acc[0][3] += a0 * b3;
            acc[1][0] += a1 * b0; acc[1][1] += a1 * b1; acc[1][2] += a1 * b2; acc[1][3] += a1 * b3;
            acc[2][0] += a2 * b0; acc[2][1] += a2 * b1; acc[2][2] += a2 * b2; acc[2][3] += a2 * b3;
            acc[3][0] += a3 * b0; acc[3][1] += a3 * b1; acc[3][2] += a3 * b2; acc[3][3] += a3 * b3;
        }
        __syncthreads();
    }
    #pragma unroll
    for (int i = 0; i < 4; i++)
        #pragma unroll
        for (int j = 0; j < 4; j++)
            S[(size_t)(m0 + ty * 4 + i) * 512 + n0 + tx * 4 + j] = acc[i][j];
}

// ======================= softmax =======================
__global__ void softmax_kernel()
{
    int row = blockIdx.x;
    float* s = g_S + (size_t)row * 512;
    int tid = threadIdx.x;

    float v0 = s[tid], v1 = s[tid + 256];
    float m = fmaxf(v0, v1);
    __shared__ float red[8];
    #pragma unroll
    for (int o = 16; o > 0; o >>= 1)
        m = fmaxf(m, __shfl_xor_sync(0xffffffffu, m, o));
    if ((tid & 31) == 0) red[tid >> 5] = m;
    __syncthreads();
    float M = fmaxf(fmaxf(fmaxf(red[0], red[1]), fmaxf(red[2], red[3])),
                    fmaxf(fmaxf(red[4], red[5]), fmaxf(red[6], red[7])));
    __syncthreads();

    float e0 = expf(v0 - M), e1 = expf(v1 - M);
    float sum = e0 + e1;
    #pragma unroll
    for (int o = 16; o > 0; o >>= 1)
        sum += __shfl_xor_sync(0xffffffffu, sum, o);
    if ((tid & 31) == 0) red[tid >> 5] = sum;
    __syncthreads();
    float T = red[0] + red[1] + red[2] + red[3] + red[4] + red[5] + red[6] + red[7];
    float inv = 1.0f / T;
    s[tid] = e0 * inv;
    s[tid + 256] = e1 * inv;
}

// ======================= out GEMM (fp32) =======================
__global__ __launch_bounds__(256) void out_kernel(
    const float* __restrict__ x, const float* __restrict__ beta,
    float* __restrict__ out)
{
    int b = blockIdx.z;
    const float* A = g_S + (size_t)b * 512 * 512;
    const float* X = x + (size_t)b * 512 * 1024;
    float* O = out + (size_t)b * 512 * 1024;

    int m0 = blockIdx.y * 64, n0 = blockIdx.x * 64;
    __shared__ float sA[16][65];
    __shared__ __align__(16) float sB[16][64];

    int tid = threadIdx.x;
    int ty = tid >> 4, tx = tid & 15;
    float acc[4][4] = {};

    for (int k0 = 0; k0 < 512; k0 += 16) {
        #pragma unroll
        for (int i = 0; i < 4; i++) {
            int idx = tid + i * 256;
            int m = idx >> 4, k = idx & 15;
            sA[k][m] = A[(size_t)(m0 + m) * 512 + k0 + k];
        }
        #pragma unroll
        for (int i = 0; i < 4; i++) {
            int idx = tid + i * 256;
            int k = idx >> 6, n = idx & 63;
            sB[k][n] = X[(size_t)(k0 + k) * 1024 + n0 + n];
        }
        __syncthreads();
        #pragma unroll
        for (int k = 0; k < 16; k++) {
            float a0 = sA[k][ty * 4 + 0];
            float a1 = sA[k][ty * 4 + 1];
            float a2 = sA[k][ty * 4 + 2];
            float a3 = sA[k][ty * 4 + 3];
            float4 bb = *(const float4*)&sB[k][tx * 4];
            acc[0][0] += a0 * bb.x; acc[0][1] += a0 * bb.y; acc[0][2] += a0 * bb.z; acc[0][3] += a0 * bb.w;
            acc[1][0] += a1 * bb.x; acc[1][1] += a1 * bb.y; acc[1][2] += a1 * bb.z; acc[1][3] += a1 * bb.w;
            acc[2][0] += a2 * bb.x; acc[2][1] += a2 * bb.y; acc[2][2] += a2 * bb.z; acc[2][3] += a2 * bb.w;
            acc[3][0] += a3 * bb.x; acc[3][1] += a3 * bb.y; acc[3][2] += a3 * bb.z; acc[3][3] += a3 * bb.w;
        }
        __syncthreads();
    }
    float bt = beta[0];
    #pragma unroll
    for (int i = 0; i < 4; i++)
        #pragma unroll
        for (int j = 0; j < 4; j++)
            O[(size_t)(m0 + ty * 4 + i) * 1024 + n0 + tx * 4 + j] = bt * acc[i][j];
}

// ======================= launch =======================
extern "C" void kernel_launch(void* const* d_in, const int* in_sizes, int n_in,
                              void* d_out, int out_size)
{
    const float* x     = (const float*)d_in[0];
    const float* x1    = (const float*)d_in[1];
    const float* x2    = (const float*)d_in[2];
    const float* w1    = (const float*)d_in[3];
    const float* b1    = (const float*)d_in[4];
    const float* w2    = (const float*)d_in[5];
    const float* b2    = (const float*)d_in[6];
    const float* gamma = (const float*)d_in[7];
    const float* bnb   = (const float*)d_in[8];
    const float* beta  = (const float*)d_in[9];
    float* out = (float*)d_out;

    static int smem_set = 0;
    if (!smem_set) {
        cudaFuncSetAttribute(conv3x3_mma_kernel,
                             cudaFuncAttributeMaxDynamicSharedMemorySize, SMEM_CONV);
        smem_set = 1;
    }

    zero_ypad_kernel<<<(16 * 256 * YSTRIDE + 255) / 256, 256>>>();
    areorder_kernel<<<(9 * 8 * 4 * 4096) / 256, 256>>>(w2);

    conv1x1_kernel<<<dim3(16, 4, 16), 256>>>(x1, x2, w1, b1);

    conv3x3_mma_kernel<<<dim3(9, 4, 16), 256, SMEM_CONV>>>(b2);

    bn_stats_kernel<<<4, 256>>>(gamma, bnb);
    bn_apply_kernel<<<(2 * 8 * 512 * 1024) / 256, 256>>>();

    scores_kernel<<<dim3(8, 8, 8), 256>>>();
    softmax_kernel<<<4096, 256>>>();

    out_kernel<<<dim3(16, 8, 8), 256>>>(x, beta, out);
}

// round 5
// speedup vs baseline: 3.0295x; 1.3380x over previous
#include <cuda_runtime.h>
#include <cstdint>
#include <math.h>

// ======================= device scratch =======================
#define YSTRIDE 1408
// conv1x1 output, tf32-split, zero-padded 34-wide layout [16][256][YSTRIDE]
__device__ __align__(16) float g_Yhi[16 * 256 * YSTRIDE];
__device__ __align__(16) float g_Ylo[16 * 256 * YSTRIDE];
// conv3x3 weights reordered fragment-major: [tap9][cc8][m0t4][4096]
__device__ __align__(16) float g_Aord[9 * 8 * 4 * 4096];
// conv3x3 outputs (pre-BN, then normalized in place) [2][8][512][1024]
__device__ __align__(16) float g_F[2 * 8 * 512 * 1024];
// attention scores [8][512][512]
__device__ __align__(16) float g_S[8 * 512 * 512];
// BN partials: [t*512+co][144]  (b(8) x ntile(9) x ncol(2))
__device__ float g_psum[1024 * 144];
__device__ float g_psumq[1024 * 144];

#define LRELU 0.01f
#define BN_EPS 1e-5f
#define BSTRIDE 204

__device__ __forceinline__ float tf32r(float x) {
    float r; asm("cvt.rna.tf32.f32 %0, %1;" : "=f"(r) : "f"(x)); return r;
}
__device__ __forceinline__ uint32_t fu(float x) { return __float_as_uint(x); }
__device__ __forceinline__ uint32_t smem_u32(const void* p) {
    uint32_t a;
    asm("{ .reg .u64 t; cvta.to.shared.u64 t, %1; cvt.u32.u64 %0, t; }" : "=r"(a) : "l"(p));
    return a;
}

#define MMA_TF32(d, a0, a1, a2, a3, b0v, b1v) \
    asm volatile("mma.sync.aligned.m16n8k8.row.col.f32.tf32.tf32.f32 " \
        "{%0,%1,%2,%3}, {%4,%5,%6,%7}, {%8,%9}, {%0,%1,%2,%3};" \
        : "+f"((d)[0]), "+f"((d)[1]), "+f"((d)[2]), "+f"((d)[3]) \
        : "r"(a0), "r"(a1), "r"(a2), "r"(a3), "r"(b0v), "r"(b1v))

#define CP16(saddr, gptr) \
    asm volatile("cp.async.ca.shared.global [%0], [%1], 16;" \
                 :: "r"((uint32_t)(saddr)), "l"(gptr) : "memory")
#define CP_COMMIT() asm volatile("cp.async.commit_group;" ::: "memory")
#define CP_WAIT_ALL() asm volatile("cp.async.wait_group 0;" ::: "memory")

// ======================= setup kernels =======================
__global__ void zero_ypad_kernel() {
    int i = blockIdx.x * 256 + threadIdx.x;
    if (i < 16 * 256 * YSTRIDE) { g_Yhi[i] = 0.f; g_Ylo[i] = 0.f; }
}

// Reorder w2 into fragment-major: [tap][cc][m0t][mblk8][s4][lane32][c4]
__global__ void areorder_kernel(const float* __restrict__ w2) {
    int idx = blockIdx.x * 256 + threadIdx.x;
    if (idx >= 9 * 8 * 4 * 4096) return;
    int c    = idx & 3;
    int lane = (idx >> 2) & 31;
    int s    = (idx >> 7) & 3;
    int mblk = (idx >> 9) & 7;
    int m0t  = (idx >> 12) & 3;
    int cc   = (idx >> 14) & 7;
    int tap  = idx >> 17;
    int m = mblk * 16 + (lane >> 2) + (c & 1) * 8;
    int k = (lane & 3) + (c >> 1) * 4;
    int co = m0t * 128 + m;
    int ci = cc * 32 + s * 8 + k;
    g_Aord[idx] = w2[(size_t)co * 2304 + ci * 9 + tap];
}

// ======================= conv 1x1 via mma (tf32 3-split) -> Yhi/Ylo ======
// CTA 128m x 128n, K=512 (16 chunks of 32). A = w1 [m][k]; B = X [k][n].
// smem: A 2 x 128x36 (stride 36), B 2 x 32x140 (stride 140)
#define SMEM_C1 ((2 * 128 * 36 + 2 * 32 * 140) * 4)
__global__ __launch_bounds__(256, 2) void conv1x1_mma_kernel(
    const float* __restrict__ x1, const float* __restrict__ x2,
    const float* __restrict__ w1, const float* __restrict__ b1)
{
    extern __shared__ __align__(16) float smem[];
    float* sA = smem;                 // 2 x 4608
    float* sB = smem + 2 * 4608;      // 2 x 4480
    uint32_t sA32 = smem_u32(sA), sB32 = smem_u32(sB);

    int tid = threadIdx.x, wid = tid >> 5, lane = tid & 31;
    int g = lane >> 2, tq = lane & 3;
    int n0 = blockIdx.x * 128;
    int m0 = blockIdx.y * 128;
    int z = blockIdx.z;
    const float* X = ((z >> 3) ? x2 : x1) + (size_t)(z & 7) * 512 * 1024;

    int wm = (wid & 3) * 32, wn = (wid >> 2) * 64;

    float acc[2][8][4];
    #pragma unroll
    for (int i = 0; i < 2; i++)
        #pragma unroll
        for (int j = 0; j < 8; j++)
            #pragma unroll
            for (int r = 0; r < 4; r++) acc[i][j][r] = 0.f;

    auto stageA = [&](int kc) {
        uint32_t base = sA32 + (uint32_t)((kc & 1) * 4608) * 4;
        #pragma unroll
        for (int v = 0; v < 4; v++) {
            int task = tid + v * 256;
            int m = task >> 3, c4 = task & 7;
            CP16(base + (m * 36 + c4 * 4) * 4, w1 + (size_t)(m0 + m) * 512 + kc * 32 + c4 * 4);
        }
    };
    auto stageB = [&](int kc) {
        uint32_t base = sB32 + (uint32_t)((kc & 1) * 4480) * 4;
        #pragma unroll
        for (int v = 0; v < 4; v++) {
            int task = tid + v * 256;
            int k = task >> 5, c4 = task & 31;
            CP16(base + (k * 140 + c4 * 4) * 4, X + (size_t)(kc * 32 + k) * 1024 + n0 + c4 * 4);
        }
    };

    stageA(0); stageB(0); CP_COMMIT();

    for (int kc = 0; kc < 16; kc++) {
        CP_WAIT_ALL();
        __syncthreads();
        if (kc < 15) { stageA(kc + 1); stageB(kc + 1); }
        CP_COMMIT();
        const float* sAp = sA + (kc & 1) * 4608;
        const float* sBp = sB + (kc & 1) * 4480;
        #pragma unroll
        for (int s = 0; s < 4; s++) {
            uint32_t ah[2][4], al[2][4];
            #pragma unroll
            for (int i = 0; i < 2; i++) {
                const float* ap = sAp + (wm + i * 16 + g) * 36 + s * 8 + tq;
                float a0 = ap[0], a1 = ap[8 * 36], a2 = ap[4], a3 = ap[8 * 36 + 4];
                float h0 = tf32r(a0), h1 = tf32r(a1), h2 = tf32r(a2), h3 = tf32r(a3);
                ah[i][0] = fu(h0); ah[i][1] = fu(h1); ah[i][2] = fu(h2); ah[i][3] = fu(h3);
                al[i][0] = fu(a0 - h0); al[i][1] = fu(a1 - h1);
                al[i][2] = fu(a2 - h2); al[i][3] = fu(a3 - h3);
            }
            const float* brow = sBp + (s * 8 + tq) * 140 + wn + g;
            #pragma unroll
            for (int j = 0; j < 8; j++) {
                float b0 = brow[j * 8], b1 = brow[j * 8 + 4 * 140];
                float bh0 = tf32r(b0), bh1 = tf32r(b1);
                uint32_t ubh0 = fu(bh0), ubh1 = fu(bh1);
                uint32_t ubl0 = fu(b0 - bh0), ubl1 = fu(b1 - bh1);
                #pragma unroll
                for (int i = 0; i < 2; i++) {
                    MMA_TF32(acc[i][j], ah[i][0], ah[i][1], ah[i][2], ah[i][3], ubh0, ubh1);
                    MMA_TF32(acc[i][j], al[i][0], al[i][1], al[i][2], al[i][3], ubh0, ubh1);
                    MMA_TF32(acc[i][j], ah[i][0], ah[i][1], ah[i][2], ah[i][3], ubl0, ubl1);
                }
            }
        }
    }

    // epilogue: bias, tf32-split, scatter to Yhi/Ylo padded layout
    size_t zoff = (size_t)z * 256 * YSTRIDE;
    #pragma unroll
    for (int i = 0; i < 2; i++) {
        #pragma unroll
        for (int rh = 0; rh < 2; rh++) {
            int m = m0 + wm + i * 16 + g + rh * 8;
            float bias = b1[m];
            #pragma unroll
            for (int j = 0; j < 8; j++) {
                #pragma unroll
                for (int c = 0; c < 2; c++) {
                    float v = acc[i][j][rh * 2 + c] + bias;
                    int p = n0 + wn + j * 8 + 2 * tq + c;
                    size_t idx = zoff + (size_t)m * YSTRIDE + 99 + (p >> 5) * 34 + (p & 31);
                    float hi = tf32r(v);
                    g_Yhi[idx] = hi;
                    g_Ylo[idx] = v - hi;
                }
            }
        }
    }
}

// ======================= conv 3x3 via mma.sync tf32 (v3) ==========
// CTA: D[128 co][128 n']. Chunks: cc(8) outer x tap(9) inner.
// A: fragment-major fp32 (split in regs), double-buffered (2 x 16KB).
// B: pre-split hi/lo rows [32k][204], single-buffered (2 x 25.5KB), staged per cc.
#define SMEM_CONV ((2 * 4096 + 2 * 32 * BSTRIDE) * 4)

__global__ __launch_bounds__(256, 2) void conv3x3_mma_kernel(const float* __restrict__ b2)
{
    extern __shared__ __align__(16) float smem[];
    float* sA = smem;                 // 2 x 4096
    float* sB = smem + 2 * 4096;      // hi 6528, lo 6528
    uint32_t sA32 = smem_u32(sA), sB32 = smem_u32(sB);

    int tid = threadIdx.x, wid = tid >> 5, lane = tid & 31;
    int g = lane >> 2, tq = lane & 3;
    int ntile = blockIdx.x;              // 0..8
    int m0y = blockIdx.y;
    int m0 = m0y * 128;
    int z = blockIdx.z;
    int nbase = ntile * 128;
    size_t zoff = (size_t)z * 256 * YSTRIDE;

    int aoff = (29 + nbase) & 3;
    int colbase = (29 + nbase) - aoff;

    int wm = (wid & 3) * 32, wn = (wid >> 2) * 64;

    float acc[2][8][4];
    #pragma unroll
    for (int i = 0; i < 2; i++)
        #pragma unroll
        for (int j = 0; j < 8; j++)
            #pragma unroll
            for (int r = 0; r < 4; r++) acc[i][j][r] = 0.f;

    auto stageA = [&](int it) {
        int tap = it % 9, cc = it / 9;
        const float4* gA = (const float4*)(g_Aord + (((size_t)tap * 8 + cc) * 4 + m0y) * 4096);
        uint32_t base = sA32 + (uint32_t)((it & 1) * 4096) * 4;
        #pragma unroll
        for (int v = 0; v < 4; v++) {
            int e = tid + v * 256;
            CP16(base + e * 16, gA + e);
        }
    };
    auto stageB = [&](int cc) {
        #pragma unroll
        for (int v = 0; v < 13; v++) {
            int i = tid + v * 256;
            if (i < 2 * 32 * 51) {
                int arr = i >= 32 * 51;
                int rem = i - arr * (32 * 51);
                int row = rem / 51;
                int c4 = rem - row * 51;
                const float* src = (arr ? g_Ylo : g_Yhi) + zoff
                                   + (size_t)(cc * 32 + row) * YSTRIDE + colbase + c4 * 4;
                CP16(sB32 + (arr * 6528 + row * BSTRIDE + c4 * 4) * 4, src);
            }
        }
    };

    stageA(0);
    stageB(0);
    CP_COMMIT();

    for (int it = 0; it < 72; ++it) {
        int tap = it % 9, cc = it / 9;
        int dh = tap / 3, dw = tap - dh * 3;

        CP_WAIT_ALL();
        __syncthreads();

        if (it < 71) stageA(it + 1);
        CP_COMMIT();

        const float* sAp = sA + (it & 1) * 4096;
        const float* sBh = sB + aoff + dh * 34 + dw;
        const float* sBl = sBh + 6528;

        #pragma unroll
        for (int s = 0; s < 4; s++) {
            uint32_t ah[2][4], al[2][4];
            #pragma unroll
            for (int i = 0; i < 2; i++) {
                int mblk = (wm >> 4) + i;
                float4 av = *(const float4*)&sAp[((mblk * 4 + s) * 32 + lane) * 4];
                float h0 = tf32r(av.x), h1 = tf32r(av.y), h2 = tf32r(av.z), h3 = tf32r(av.w);
                ah[i][0] = fu(h0); ah[i][1] = fu(h1); ah[i][2] = fu(h2); ah[i][3] = fu(h3);
                al[i][0] = fu(av.x - h0); al[i][1] = fu(av.y - h1);
                al[i][2] = fu(av.z - h2); al[i][3] = fu(av.w - h3);
            }
            const float* bhrow = sBh + (s * 8 + tq) * BSTRIDE + wn + g;
            const float* blrow = sBl + (s * 8 + tq) * BSTRIDE + wn + g;
            #pragma unroll
            for (int j = 0; j < 8; j++) {
                uint32_t ubh0 = fu(bhrow[j * 8]);
                uint32_t ubh1 = fu(bhrow[j * 8 + 4 * BSTRIDE]);
                uint32_t ubl0 = fu(blrow[j * 8]);
                uint32_t ubl1 = fu(blrow[j * 8 + 4 * BSTRIDE]);
                #pragma unroll
                for (int i = 0; i < 2; i++) {
                    MMA_TF32(acc[i][j], ah[i][0], ah[i][1], ah[i][2], ah[i][3], ubh0, ubh1);
                    MMA_TF32(acc[i][j], al[i][0], al[i][1], al[i][2], al[i][3], ubh0, ubh1);
                    MMA_TF32(acc[i][j], ah[i][0], ah[i][1], ah[i][2], ah[i][3], ubl0, ubl1);
                }
            }
        }

        // stage next cc's B after all warps finished reading this cc (tap==8)
        if (tap == 8 && cc < 7) {
            __syncthreads();
            stageB(cc + 1);
            CP_COMMIT();
        }
    }

    // ---- epilogue: bias + LeakyReLU + store F + BN partials ----
    int timg = z >> 3, b = z & 7;
    int ncol = wid >> 2;
    float bias[2][2], psv[2][2] = {}, pqv[2][2] = {};
    #pragma unroll
    for (int i = 0; i < 2; i++)
        #pragma unroll
        for (int rh = 0; rh < 2; rh++)
            bias[i][rh] = b2[m0 + wm + i * 16 + g + rh * 8];

    #pragma unroll
    for (int i = 0; i < 2; i++) {
        #pragma unroll
        for (int j = 0; j < 8; j++) {
            #pragma unroll
            for (int r = 0; r < 4; r++) {
                int rh = r >> 1, c = r & 1;
                int m = wm + i * 16 + g + rh * 8;
                int np = nbase + wn + j * 8 + 2 * tq + c;
                int row = np / 34;
                int col = np - row * 34;
                if (row >= 1 && row <= 32 && col >= 1 && col <= 32) {
                    float v = acc[i][j][r] + bias[i][rh];
                    v = v > 0.f ? v : LRELU * v;
                    g_F[((size_t)z * 512 + m0 + m) * 1024 + (row - 1) * 32 + (col - 1)] = v;
                    psv[i][rh] += v;
                    pqv[i][rh] += v * v;
                }
            }
        }
    }
    #pragma unroll
    for (int i = 0; i < 2; i++) {
        #pragma unroll
        for (int rh = 0; rh < 2; rh++) {
            float s = psv[i][rh], q = pqv[i][rh];
            s += __shfl_xor_sync(0xffffffffu, s, 1);
            s += __shfl_xor_sync(0xffffffffu, s, 2);
            q += __shfl_xor_sync(0xffffffffu, q, 1);
            q += __shfl_xor_sync(0xffffffffu, q, 2);
            if (tq == 0) {
                int ch = timg * 512 + m0 + wm + i * 16 + g + rh * 8;
                int slot = (b * 9 + ntile) * 2 + ncol;
                g_psum [(size_t)ch * 144 + slot] = s;
                g_psumq[(size_t)ch * 144 + slot] = q;
            }
        }
    }
}

// ======================= BN stats / apply =======================
__device__ float g_bn_a[1024];
__device__ float g_bn_c[1024];

__global__ void bn_stats_kernel(const float* __restrict__ gamma,
                                const float* __restrict__ bn_bias)
{
    int i = blockIdx.x * blockDim.x + threadIdx.x;
    if (i >= 1024) return;
    float s = 0.f, q = 0.f;
    #pragma unroll 8
    for (int p = 0; p < 144; p++) {
        s += g_psum [(size_t)i * 144 + p];
        q += g_psumq[(size_t)i * 144 + p];
    }
    const float inv_n = 1.0f / 8192.0f;
    float mean = s * inv_n;
    float var = q * inv_n - mean * mean;
    float a = gamma[i & 511] * rsqrtf(var + BN_EPS);
    g_bn_a[i] = a;
    g_bn_c[i] = bn_bias[i & 511] - mean * a;
}

__global__ void bn_apply_kernel()
{
    int idx = blockIdx.x * 256 + threadIdx.x;
    int ch = (idx >> 10) & 511;
    int t = idx >> 22;
    float v = g_F[idx];
    g_F[idx] = v * g_bn_a[t * 512 + ch] + g_bn_c[t * 512 + ch];
}

// ======================= scores GEMM via mma (tf32 3-split) =======
// S[b] = F1[b] * F2[b]^T. M=N=512, K=1024 (32 chunks). Both operands K-contig.
// smem: A 2 x 128x36, B 2 x 128x36
#define SMEM_SC ((4 * 128 * 36) * 4)
__global__ __launch_bounds__(256, 2) void scores_mma_kernel()
{
    extern __shared__ __align__(16) float smem[];
    float* sA = smem;               // 2 x 4608
    float* sB = smem + 2 * 4608;    // 2 x 4608
    uint32_t sA32 = smem_u32(sA), sB32 = smem_u32(sB);

    int tid = threadIdx.x, wid = tid >> 5, lane = tid & 31;
    int g = lane >> 2, tq = lane & 3;
    int n0 = blockIdx.x * 128, m0 = blockIdx.y * 128, b = blockIdx.z;
    const float* Ag = g_F + (size_t)b * 512 * 1024;
    const float* Bg = g_F + (size_t)(8 + b) * 512 * 1024;

    int wm = (wid & 3) * 32, wn = (wid >> 2) * 64;

    float acc[2][8][4];
    #pragma unroll
    for (int i = 0; i < 2; i++)
        #pragma unroll
        for (int j = 0; j < 8; j++)
            #pragma unroll
            for (int r = 0; r < 4; r++) acc[i][j][r] = 0.f;

    auto stage = [&](int kc) {
        uint32_t baseA = sA32 + (uint32_t)((kc & 1) * 4608) * 4;
        uint32_t baseB = sB32 + (uint32_t)((kc & 1) * 4608) * 4;
        #pragma unroll
        for (int v = 0; v < 4; v++) {
            int task = tid + v * 256;
            int m = task >> 3, c4 = task & 7;
            CP16(baseA + (m * 36 + c4 * 4) * 4, Ag + (size_t)(m0 + m) * 1024 + kc * 32 + c4 * 4);
            CP16(baseB + (m * 36 + c4 * 4) * 4, Bg + (size_t)(n0 + m) * 1024 + kc * 32 + c4 * 4);
        }
    };

    stage(0); CP_COMMIT();

    for (int kc = 0; kc < 32; kc++) {
        CP_WAIT_ALL();
        __syncthreads();
        if (kc < 31) stage(kc + 1);
        CP_COMMIT();
        const float* sAp = sA + (kc & 1) * 4608;
        const float* sBp = sB + (kc & 1) * 4608;
        #pragma unroll
        for (int s = 0; s < 4; s++) {
            uint32_t ah[2][4], al[2][4];
            #pragma unroll
            for (int i = 0; i < 2; i++) {
                const float* ap = sAp + (wm + i * 16 + g) * 36 + s * 8 + tq;
                float a0 = ap[0], a1 = ap[8 * 36], a2 = ap[4], a3 = ap[8 * 36 + 4];
                float h0 = tf32r(a0), h1 = tf32r(a1), h2 = tf32r(a2), h3 = tf32r(a3);
                ah[i][0] = fu(h0); ah[i][1] = fu(h1); ah[i][2] = fu(h2); ah[i][3] = fu(h3);
                al[i][0] = fu(a0 - h0); al[i][1] = fu(a1 - h1);
                al[i][2] = fu(a2 - h2); al[i][3] = fu(a3 - h3);
            }
            #pragma unroll
            for (int j = 0; j < 8; j++) {
                const float* bp = sBp + (wn + j * 8 + g) * 36 + s * 8 + tq;
                float b0 = bp[0], b1 = bp[4];
                float bh0 = tf32r(b0), bh1 = tf32r(b1);
                uint32_t ubh0 = fu(bh0), ubh1 = fu(bh1);
                uint32_t ubl0 = fu(b0 - bh0), ubl1 = fu(b1 - bh1);
                #pragma unroll
                for (int i = 0; i < 2; i++) {
                    MMA_TF32(acc[i][j], ah[i][0], ah[i][1], ah[i][2], ah[i][3], ubh0, ubh1);
                    MMA_TF32(acc[i][j], al[i][0], al[i][1], al[i][2], al[i][3], ubh0, ubh1);
                    MMA_TF32(acc[i][j], ah[i][0], ah[i][1], ah[i][2], ah[i][3], ubl0, ubl1);
                }
            }
        }
    }

    float* S = g_S + (size_t)b * 512 * 512;
    #pragma unroll
    for (int i = 0; i < 2; i++)
        #pragma unroll
        for (int j = 0; j < 8; j++)
            #pragma unroll
            for (int r = 0; r < 4; r++) {
                int m = m0 + wm + i * 16 + g + (r >> 1) * 8;
                int n = n0 + wn + j * 8 + 2 * tq + (r & 1);
                S[(size_t)m * 512 + n] = acc[i][j][r];
            }
}

// ======================= softmax =======================
__global__ void softmax_kernel()
{
    int row = blockIdx.x;
    float* s = g_S + (size_t)row * 512;
    int tid = threadIdx.x;

    float v0 = s[tid], v1 = s[tid + 256];
    float m = fmaxf(v0, v1);
    __shared__ float red[8];
    #pragma unroll
    for (int o = 16; o > 0; o >>= 1)
        m = fmaxf(m, __shfl_xor_sync(0xffffffffu, m, o));
    if ((tid & 31) == 0) red[tid >> 5] = m;
    __syncthreads();
    float M = fmaxf(fmaxf(fmaxf(red[0], red[1]), fmaxf(red[2], red[3])),
                    fmaxf(fmaxf(red[4], red[5]), fmaxf(red[6], red[7])));
    __syncthreads();

    float e0 = expf(v0 - M), e1 = expf(v1 - M);
    float sum = e0 + e1;
    #pragma unroll
    for (int o = 16; o > 0; o >>= 1)
        sum += __shfl_xor_sync(0xffffffffu, sum, o);
    if ((tid & 31) == 0) red[tid >> 5] = sum;
    __syncthreads();
    float T = red[0] + red[1] + red[2] + red[3] + red[4] + red[5] + red[6] + red[7];
    float inv = 1.0f / T;
    s[tid] = e0 * inv;
    s[tid + 256] = e1 * inv;
}

// ======================= out GEMM via mma (tf32 3-split) ==========
// O[b] = beta * Attn[b] * X[b]. M=512, N=1024, K=512 (16 chunks).
// A = S [m][k] k-contig; B = x [k][n] n-contig.
#define SMEM_OUT ((2 * 128 * 36 + 2 * 32 * 140) * 4)
__global__ __launch_bounds__(256, 2) void out_mma_kernel(
    const float* __restrict__ x, const float* __restrict__ beta,
    float* __restrict__ out)
{
    extern __shared__ __align__(16) float smem[];
    float* sA = smem;                 // 2 x 4608
    float* sB = smem + 2 * 4608;      // 2 x 4480
    uint32_t sA32 = smem_u32(sA), sB32 = smem_u32(sB);

    int tid = threadIdx.x, wid = tid >> 5, lane = tid & 31;
    int g = lane >> 2, tq = lane & 3;
    int n0 = blockIdx.x * 128, m0 = blockIdx.y * 128, b = blockIdx.z;
    const float* Ag = g_S + (size_t)b * 512 * 512;
    const float* X = x + (size_t)b * 512 * 1024;

    int wm = (wid & 3) * 32, wn = (wid >> 2) * 64;

    float acc[2][8][4];
    #pragma unroll
    for (int i = 0; i < 2; i++)
        #pragma unroll
        for (int j = 0; j < 8; j++)
            #pragma unroll
            for (int r = 0; r < 4; r++) acc[i][j][r] = 0.f;

    auto stageA = [&](int kc) {
        uint32_t base = sA32 + (uint32_t)((kc & 1) * 4608) * 4;
        #pragma unroll
        for (int v = 0; v < 4; v++) {
            int task = tid + v * 256;
            int m = task >> 3, c4 = task & 7;
            CP16(base + (m * 36 + c4 * 4) * 4, Ag + (size_t)(m0 + m) * 512 + kc * 32 + c4 * 4);
        }
    };
    auto stageB = [&](int kc) {
        uint32_t base = sB32 + (uint32_t)((kc & 1) * 4480) * 4;
        #pragma unroll
        for (int v = 0; v < 4; v++) {
            int task = tid + v * 256;
            int k = task >> 5, c4 = task & 31;
            CP16(base + (k * 140 + c4 * 4) * 4, X + (size_t)(kc * 32 + k) * 1024 + n0 + c4 * 4);
        }
    };

    stageA(0); stageB(0); CP_COMMIT();

    for (int kc = 0; kc < 16; kc++) {
        CP_WAIT_ALL();
        __syncthreads();
        if (kc < 15) { stageA(kc + 1); stageB(kc + 1); }
        CP_COMMIT();
        const float* sAp = sA + (kc & 1) * 4608;
        const float* sBp = sB + (kc & 1) * 4480;
        #pragma unroll
        for (int s = 0; s < 4; s++) {
            uint32_t ah[2][4], al[2][4];
            #pragma unroll
            for (int i = 0; i < 2; i++) {
                const float* ap = sAp + (wm + i * 16 + g) * 36 + s * 8 + tq;
                float a0 = ap[0], a1 = ap[8 * 36], a2 = ap[4], a3 = ap[8 * 36 + 4];
                float h0 = tf32r(a0), h1 = tf32r(a1), h2 = tf32r(a2), h3 = tf32r(a3);
                ah[i][0] = fu(h0); ah[i][1] = fu(h1); ah[i][2] = fu(h2); ah[i][3] = fu(h3);
                al[i][0] = fu(a0 - h0); al[i][1] = fu(a1 - h1);
                al[i][2] = fu(a2 - h2); al[i][3] = fu(a3 - h3);
            }
            const float* brow = sBp + (s * 8 + tq) * 140 + wn + g;
            #pragma unroll
            for (int j = 0; j < 8; j++) {
                float b0 = brow[j * 8], b1 = brow[j * 8 + 4 * 140];
                float bh0 = tf32r(b0), bh1 = tf32r(b1);
                uint32_t ubh0 = fu(bh0), ubh1 = fu(bh1);
                uint32_t ubl0 = fu(b0 - bh0), ubl1 = fu(b1 - bh1);
                #pragma unroll
                for (int i = 0; i < 2; i++) {
                    MMA_TF32(acc[i][j], ah[i][0], ah[i][1], ah[i][2], ah[i][3], ubh0, ubh1);
                    MMA_TF32(acc[i][j], al[i][0], al[i][1], al[i][2], al[i][3], ubh0, ubh1);
                    MMA_TF32(acc[i][j], ah[i][0], ah[i][1], ah[i][2], ah[i][3], ubl0, ubl1);
                }
            }
        }
    }

    float bt = beta[0];
    float* O = out + (size_t)b * 512 * 1024;
    #pragma unroll
    for (int i = 0; i < 2; i++)
        #pragma unroll
        for (int j = 0; j < 8; j++)
            #pragma unroll
            for (int r = 0; r < 4; r++) {
                int m = m0 + wm + i * 16 + g + (r >> 1) * 8;
                int n = n0 + wn + j * 8 + 2 * tq + (r & 1);
                O[(size_t)m * 1024 + n] = bt * acc[i][j][r];
            }
}

// ======================= launch =======================
extern "C" void kernel_launch(void* const* d_in, const int* in_sizes, int n_in,
                              void* d_out, int out_size)
{
    const float* x     = (const float*)d_in[0];
    const float* x1    = (const float*)d_in[1];
    const float* x2    = (const float*)d_in[2];
    const float* w1    = (const float*)d_in[3];
    const float* b1    = (const float*)d_in[4];
    const float* w2    = (const float*)d_in[5];
    const float* b2    = (const float*)d_in[6];
    const float* gamma = (const float*)d_in[7];
    const float* bnb   = (const float*)d_in[8];
    const float* beta  = (const float*)d_in[9];
    float* out = (float*)d_out;

    static int smem_set = 0;
    if (!smem_set) {
        cudaFuncSetAttribute(conv1x1_mma_kernel, cudaFuncAttributeMaxDynamicSharedMemorySize, SMEM_C1);
        cudaFuncSetAttribute(conv3x3_mma_kernel, cudaFuncAttributeMaxDynamicSharedMemorySize, SMEM_CONV);
        cudaFuncSetAttribute(scores_mma_kernel,  cudaFuncAttributeMaxDynamicSharedMemorySize, SMEM_SC);
        cudaFuncSetAttribute(out_mma_kernel,     cudaFuncAttributeMaxDynamicSharedMemorySize, SMEM_OUT);
        smem_set = 1;
    }

    zero_ypad_kernel<<<(16 * 256 * YSTRIDE + 255) / 256, 256>>>();
    areorder_kernel<<<(9 * 8 * 4 * 4096) / 256, 256>>>(w2);

    conv1x1_mma_kernel<<<dim3(8, 2, 16), 256, SMEM_C1>>>(x1, x2, w1, b1);

    conv3x3_mma_kernel<<<dim3(9, 4, 16), 256, SMEM_CONV>>>(b2);

    bn_stats_kernel<<<4, 256>>>(gamma, bnb);
    bn_apply_kernel<<<(2 * 8 * 512 * 1024) / 256, 256>>>();

    scores_mma_kernel<<<dim3(4, 4, 8), 256, SMEM_SC>>>();
    softmax_kernel<<<4096, 256>>>();

    out_mma_kernel<<<dim3(8, 4, 8), 256, SMEM_OUT>>>(x, beta, out);
}